// round 12
// baseline (speedup 1.0000x reference)
#include <cuda_runtime.h>

// AuxIVA: K=4 sources, F=513 freqs, B=4000 frames, 5 iterations.
// d_in[0]=Xr (K,F,B) f32, d_in[1]=Xi (K,F,B) f32.
// Output: float32 (K,F,B) = real part of projected-back demixed signal.

#define K_DIM 4
#define F_DIM 513
#define B_DIM 4000
#define B4    (B_DIM / 4)          // 1000 float4 per (k,f) row
#define FB    (F_DIM * B_DIM)
#define FB4   (FB / 4)
#define KFB   (K_DIM * F_DIM * B_DIM)
#define N_ITER 5
#define FCH   57                   // f-chunks in k_demix
#define CHF   9                    // f per chunk (57*9 = 513)
#define NSPL  8                    // b-splits in k_V
#define NSLOT 32                   // warp slots per f in k_V (NSPL*4)

// ---------------- scratch ----------------
static __device__ float g_Whr[F_DIM * 16];             // [f][s][c]
static __device__ float g_Whi[F_DIM * 16];
static __device__ float g_part[FCH * K_DIM * B_DIM];   // [ch][k][b]
static __device__ float g_phi[K_DIM * B_DIM];          // 0.5/r, [k][b]
static __device__ float g_Vp[NSLOT * 64 * F_DIM];      // [slot][k*16+e][f]
static __device__ float g_V[64 * F_DIM];               // packed [k*16+e][f]
static __device__ float g_sclr[F_DIM * 4];             // [f][s]
static __device__ float g_scli[F_DIM * 4];

// Gauss-Jordan solve of 4x4 complex system, conditional-swap partial pivot.
static __device__ __forceinline__ void solve4(float Ar[4][4], float Ai[4][4],
                                              float ur[4], float ui[4]) {
#pragma unroll
    for (int j = 0; j < 4; j++) {
#pragma unroll
        for (int i = 0; i < 4; i++) {
            if (i > j) {
                float mj = Ar[j][j] * Ar[j][j] + Ai[j][j] * Ai[j][j];
                float mi = Ar[i][j] * Ar[i][j] + Ai[i][j] * Ai[i][j];
                if (mi > mj) {
#pragma unroll
                    for (int c = 0; c < 4; c++) {
                        float tr = Ar[j][c]; Ar[j][c] = Ar[i][c]; Ar[i][c] = tr;
                        float ti = Ai[j][c]; Ai[j][c] = Ai[i][c]; Ai[i][c] = ti;
                    }
                    float tr = ur[j]; ur[j] = ur[i]; ur[i] = tr;
                    float ti = ui[j]; ui[j] = ui[i]; ui[i] = ti;
                }
            }
        }
        float dr = Ar[j][j], di = Ai[j][j];
        float inv = 1.0f / (dr * dr + di * di);
        float pr = dr * inv, pi = -di * inv;
#pragma unroll
        for (int c = 0; c < 4; c++) {
            float ar = Ar[j][c], ai = Ai[j][c];
            Ar[j][c] = ar * pr - ai * pi;
            Ai[j][c] = ar * pi + ai * pr;
        }
        {
            float ar = ur[j], ai = ui[j];
            ur[j] = ar * pr - ai * pi;
            ui[j] = ar * pi + ai * pr;
        }
#pragma unroll
        for (int i = 0; i < 4; i++) {
            if (i != j) {
                float fr = Ar[i][j], fi = Ai[i][j];
#pragma unroll
                for (int c = 0; c < 4; c++) {
                    float ar = Ar[j][c], ai = Ai[j][c];
                    Ar[i][c] -= fr * ar - fi * ai;
                    Ai[i][c] -= fr * ai + fi * ar;
                }
                float ar = ur[j], ai = ui[j];
                ur[i] -= fr * ar - fi * ai;
                ui[i] -= fr * ai + fi * ar;
            }
        }
    }
}

// ---------------- kernels ----------------

static __global__ void k_init() {
    int i = blockIdx.x * blockDim.x + threadIdx.x;
    if (i < F_DIM * 16) {
        int rem = i & 15;
        g_Whr[i] = (rem == 0 || rem == 5 || rem == 10 || rem == 15) ? 1.f : 0.f;
        g_Whi[i] = 0.f;
    }
}

// part[ch][k][b] = sum over chunk's 9 f of |sum_c Wh[f,k,c] X[c,f,b]|^2
static __global__ void k_demix(const float4* __restrict__ Xr4,
                               const float4* __restrict__ Xi4) {
    const int ch  = blockIdx.x;                    // 0..56
    const int idx = blockIdx.y * 256 + threadIdx.x; // float4 index in b
    if (idx >= B4) return;

    float acc[4][4];                               // [s][sub-b]
#pragma unroll
    for (int s = 0; s < 4; s++)
#pragma unroll
        for (int u = 0; u < 4; u++) acc[s][u] = 0.f;

    const int f0 = ch * CHF;
    for (int fi = 0; fi < CHF; fi++) {
        const int f = f0 + fi;
        const int base4 = f * B4 + idx;
        float xr[4][4], xi[4][4];                  // [c][sub]
#pragma unroll
        for (int c = 0; c < 4; c++) {
            float4 tr = Xr4[c * FB4 + base4];
            float4 ti = Xi4[c * FB4 + base4];
            xr[c][0] = tr.x; xr[c][1] = tr.y; xr[c][2] = tr.z; xr[c][3] = tr.w;
            xi[c][0] = ti.x; xi[c][1] = ti.y; xi[c][2] = ti.z; xi[c][3] = ti.w;
        }
#pragma unroll
        for (int s = 0; s < 4; s++) {
            float wr[4], wi[4];
#pragma unroll
            for (int c = 0; c < 4; c++) {
                wr[c] = g_Whr[f * 16 + s * 4 + c];
                wi[c] = g_Whi[f * 16 + s * 4 + c];
            }
#pragma unroll
            for (int u = 0; u < 4; u++) {
                float yr = 0.f, yi = 0.f;
#pragma unroll
                for (int c = 0; c < 4; c++) {
                    yr += wr[c] * xr[c][u] - wi[c] * xi[c][u];
                    yi += wr[c] * xi[c][u] + wi[c] * xr[c][u];
                }
                acc[s][u] += yr * yr + yi * yi;
            }
        }
    }
    float4* P4 = (float4*)g_part;
#pragma unroll
    for (int s = 0; s < 4; s++) {
        float4 v;
        v.x = acc[s][0]; v.y = acc[s][1]; v.z = acc[s][2]; v.w = acc[s][3];
        P4[(ch * 4 + s) * B4 + idx] = v;
    }
}

// phi[k][b] = 0.5 / sqrt( sum_ch part[ch][k][b] )
static __global__ void k_phi() {
    int t = blockIdx.x * blockDim.x + threadIdx.x;     // (k*B4 + idx)
    if (t >= 4 * B4) return;
    const float4* P4 = (const float4*)g_part;
    const int k = t / B4, idx = t % B4;
    float4 s = make_float4(0.f, 0.f, 0.f, 0.f);
    for (int ch = 0; ch < FCH; ch++) {
        float4 v = P4[(ch * 4 + k) * B4 + idx];
        s.x += v.x; s.y += v.y; s.z += v.z; s.w += v.w;
    }
    float4 p;
    p.x = 0.5f * rsqrtf(s.x);
    p.y = 0.5f * rsqrtf(s.y);
    p.z = 0.5f * rsqrtf(s.z);
    p.w = 0.5f * rsqrtf(s.w);
    ((float4*)g_phi)[k * B4 + idx] = p;
}

// V partials: grid (F_DIM, NSPL), block 128. Each thread handles one float4
// of b (4 frames), computes the 16 Hermitian products ONCE, weights by all
// 4 phi's, warp-reduces, writes per-warp partials.
static __global__ void k_V(const float4* __restrict__ Xr4,
                           const float4* __restrict__ Xi4) {
    const int f = blockIdx.x;
    const int g = blockIdx.y * 128 + threadIdx.x;   // 0..1023 per f
    const int lane = threadIdx.x & 31;

    float acc[4][16];
#pragma unroll
    for (int k = 0; k < 4; k++)
#pragma unroll
        for (int e = 0; e < 16; e++) acc[k][e] = 0.f;

    if (g < B4) {
        const int base4 = f * B4 + g;
        float xr[4][4], xi[4][4];
#pragma unroll
        for (int c = 0; c < 4; c++) {
            float4 tr = Xr4[c * FB4 + base4];
            float4 ti = Xi4[c * FB4 + base4];
            xr[c][0] = tr.x; xr[c][1] = tr.y; xr[c][2] = tr.z; xr[c][3] = tr.w;
            xi[c][0] = ti.x; xi[c][1] = ti.y; xi[c][2] = ti.z; xi[c][3] = ti.w;
        }
        float ph[4][4];
#pragma unroll
        for (int k = 0; k < 4; k++) {
            float4 p = ((const float4*)g_phi)[k * B4 + g];
            ph[k][0] = p.x; ph[k][1] = p.y; ph[k][2] = p.z; ph[k][3] = p.w;
        }
#pragma unroll
        for (int u = 0; u < 4; u++) {
            float pr[16];
            pr[0]  = xr[0][u] * xr[0][u] + xi[0][u] * xi[0][u];
            pr[1]  = xr[1][u] * xr[1][u] + xi[1][u] * xi[1][u];
            pr[2]  = xr[2][u] * xr[2][u] + xi[2][u] * xi[2][u];
            pr[3]  = xr[3][u] * xr[3][u] + xi[3][u] * xi[3][u];
            pr[4]  = xr[0][u] * xr[1][u] + xi[0][u] * xi[1][u];
            pr[5]  = xi[0][u] * xr[1][u] - xr[0][u] * xi[1][u];
            pr[6]  = xr[0][u] * xr[2][u] + xi[0][u] * xi[2][u];
            pr[7]  = xi[0][u] * xr[2][u] - xr[0][u] * xi[2][u];
            pr[8]  = xr[0][u] * xr[3][u] + xi[0][u] * xi[3][u];
            pr[9]  = xi[0][u] * xr[3][u] - xr[0][u] * xi[3][u];
            pr[10] = xr[1][u] * xr[2][u] + xi[1][u] * xi[2][u];
            pr[11] = xi[1][u] * xr[2][u] - xr[1][u] * xi[2][u];
            pr[12] = xr[1][u] * xr[3][u] + xi[1][u] * xi[3][u];
            pr[13] = xi[1][u] * xr[3][u] - xr[1][u] * xi[3][u];
            pr[14] = xr[2][u] * xr[3][u] + xi[2][u] * xi[3][u];
            pr[15] = xi[2][u] * xr[3][u] - xr[2][u] * xi[3][u];
#pragma unroll
            for (int k = 0; k < 4; k++) {
                float p = ph[k][u];
#pragma unroll
                for (int e = 0; e < 16; e++)
                    acc[k][e] += p * pr[e];
            }
        }
    }

#pragma unroll
    for (int k = 0; k < 4; k++)
#pragma unroll
        for (int e = 0; e < 16; e++) {
#pragma unroll
            for (int off = 16; off > 0; off >>= 1)
                acc[k][e] += __shfl_down_sync(0xffffffffu, acc[k][e], off);
        }

    if (lane == 0) {
        const int slot = blockIdx.y * 4 + (threadIdx.x >> 5);   // 0..31
#pragma unroll
        for (int k = 0; k < 4; k++)
#pragma unroll
            for (int e = 0; e < 16; e++)
                g_Vp[(slot * 64 + k * 16 + e) * F_DIM + f] = acc[k][e];
    }
}

// Sum the 32 per-warp partials -> packed V (with 1/B scaling).
static __global__ void k_Vsum() {
    int t = blockIdx.x * blockDim.x + threadIdx.x;     // e64 * F_DIM + f
    if (t >= 64 * F_DIM) return;
    const int e = t / F_DIM, f = t % F_DIM;
    float s = 0.f;
#pragma unroll
    for (int slot = 0; slot < NSLOT; slot++)
        s += g_Vp[(slot * 64 + e) * F_DIM + f];
    g_V[e * F_DIM + f] = s * (1.0f / (float)B_DIM);
}

// IP updates per frequency; reads packed V, expands Hermitian in registers.
static __global__ void k_ip(int compute_scale) {
    __shared__ float sWr[16][32], sWi[16][32];
    const int tid = threadIdx.x;          // 32
    const int f = blockIdx.x * 32 + tid;
    if (f >= F_DIM) return;

#pragma unroll
    for (int e = 0; e < 16; e++) {
        sWr[e][tid] = g_Whr[f * 16 + e];
        sWi[e][tid] = g_Whi[f * 16 + e];
    }

    for (int k = 0; k < 4; k++) {
        float pk[16];
#pragma unroll
        for (int e = 0; e < 16; e++)
            pk[e] = g_V[(k * 16 + e) * F_DIM + f];
        // expand packed -> Hermitian Vk
        float Vr[4][4], Vi[4][4];
        Vr[0][0] = pk[0]; Vi[0][0] = 0.f;
        Vr[1][1] = pk[1]; Vi[1][1] = 0.f;
        Vr[2][2] = pk[2]; Vi[2][2] = 0.f;
        Vr[3][3] = pk[3]; Vi[3][3] = 0.f;
        Vr[0][1] = pk[4];  Vi[0][1] =  pk[5];  Vr[1][0] = pk[4];  Vi[1][0] = -pk[5];
        Vr[0][2] = pk[6];  Vi[0][2] =  pk[7];  Vr[2][0] = pk[6];  Vi[2][0] = -pk[7];
        Vr[0][3] = pk[8];  Vi[0][3] =  pk[9];  Vr[3][0] = pk[8];  Vi[3][0] = -pk[9];
        Vr[1][2] = pk[10]; Vi[1][2] =  pk[11]; Vr[2][1] = pk[10]; Vi[2][1] = -pk[11];
        Vr[1][3] = pk[12]; Vi[1][3] =  pk[13]; Vr[3][1] = pk[12]; Vi[3][1] = -pk[13];
        Vr[2][3] = pk[14]; Vi[2][3] =  pk[15]; Vr[3][2] = pk[14]; Vi[3][2] = -pk[15];

        float Mr[4][4], Mi[4][4];
#pragma unroll
        for (int i = 0; i < 4; i++)
#pragma unroll
            for (int j = 0; j < 4; j++) {
                float ar = 0.f, ai = 0.f;
#pragma unroll
                for (int c = 0; c < 4; c++) {
                    float wr = sWr[i * 4 + c][tid], wi = sWi[i * 4 + c][tid];
                    ar += wr * Vr[c][j] - wi * Vi[c][j];
                    ai += wr * Vi[c][j] + wi * Vr[c][j];
                }
                Mr[i][j] = ar;
                Mi[i][j] = ai;
            }
        float ur[4], ui[4];
#pragma unroll
        for (int e = 0; e < 4; e++) { ur[e] = (e == k) ? 1.f : 0.f; ui[e] = 0.f; }
        solve4(Mr, Mi, ur, ui);
        float q = 0.f;
#pragma unroll
        for (int c = 0; c < 4; c++) {
            float tr = 0.f, ti = 0.f;
#pragma unroll
            for (int j = 0; j < 4; j++) {
                tr += Vr[c][j] * ur[j] - Vi[c][j] * ui[j];
                ti += Vr[c][j] * ui[j] + Vi[c][j] * ur[j];
            }
            q += ur[c] * tr + ui[c] * ti;
        }
        float invd = rsqrtf(q);
#pragma unroll
        for (int c = 0; c < 4; c++) {
            sWr[k * 4 + c][tid] =  ur[c] * invd;
            sWi[k * 4 + c][tid] = -ui[c] * invd;
        }
    }

#pragma unroll
    for (int e = 0; e < 16; e++) {
        g_Whr[f * 16 + e] = sWr[e][tid];
        g_Whi[f * 16 + e] = sWi[e][tid];
    }

    if (compute_scale) {
        float Ar[4][4], Ai[4][4], vr[4], vi[4];
#pragma unroll
        for (int i = 0; i < 4; i++)
#pragma unroll
            for (int j = 0; j < 4; j++) {
                Ar[i][j] = sWr[i * 4 + j][tid];
                Ai[i][j] = sWi[i * 4 + j][tid];
            }
#pragma unroll
        for (int e = 0; e < 4; e++) { vr[e] = (e == 0) ? 1.f : 0.f; vi[e] = 0.f; }
        solve4(Ar, Ai, vr, vi);
#pragma unroll
        for (int c = 0; c < 4; c++) {
            g_sclr[f * 4 + c] = vr[c];
            g_scli[f * 4 + c] = vi[c];
        }
    }
}

// out[s,f,b] = Re( (sum_c Wh[f,s,c] X[c,f,b]) * scale[f,s] )
static __global__ void k_out(const float4* __restrict__ Xr4,
                             const float4* __restrict__ Xi4,
                             float4* __restrict__ out4) {
    const int f   = blockIdx.x;
    const int idx = blockIdx.y * 256 + threadIdx.x;
    if (idx >= B4) return;

    const int base4 = f * B4 + idx;
    float xr[4][4], xi[4][4];
#pragma unroll
    for (int c = 0; c < 4; c++) {
        float4 tr = Xr4[c * FB4 + base4];
        float4 ti = Xi4[c * FB4 + base4];
        xr[c][0] = tr.x; xr[c][1] = tr.y; xr[c][2] = tr.z; xr[c][3] = tr.w;
        xi[c][0] = ti.x; xi[c][1] = ti.y; xi[c][2] = ti.z; xi[c][3] = ti.w;
    }
#pragma unroll
    for (int s = 0; s < 4; s++) {
        float wr[4], wi[4];
#pragma unroll
        for (int c = 0; c < 4; c++) {
            wr[c] = g_Whr[f * 16 + s * 4 + c];
            wi[c] = g_Whi[f * 16 + s * 4 + c];
        }
        float scr = g_sclr[f * 4 + s];
        float sci = g_scli[f * 4 + s];
        float o[4];
#pragma unroll
        for (int u = 0; u < 4; u++) {
            float yr = 0.f, yi = 0.f;
#pragma unroll
            for (int c = 0; c < 4; c++) {
                yr += wr[c] * xr[c][u] - wi[c] * xi[c][u];
                yi += wr[c] * xi[c][u] + wi[c] * xr[c][u];
            }
            o[u] = yr * scr - yi * sci;
        }
        float4 v;
        v.x = o[0]; v.y = o[1]; v.z = o[2]; v.w = o[3];
        out4[s * FB4 + base4] = v;
    }
}

// ---------------- launch ----------------
extern "C" void kernel_launch(void* const* d_in, const int* in_sizes, int n_in,
                              void* d_out, int out_size) {
    if (n_in < 2) return;
    const float4* Xr4 = (const float4*)d_in[0];
    const float4* Xi4 = (const float4*)d_in[1];
    float4* out4 = (float4*)d_out;

    dim3 gD(FCH, 4);          // k_demix: 57 x 4 blocks, 256 thr
    dim3 gV(F_DIM, NSPL);     // k_V:     513 x 8 blocks, 128 thr
    dim3 gO(F_DIM, 4);        // k_out:   513 x 4 blocks, 256 thr

    k_init<<<33, 256>>>();
    for (int it = 0; it < N_ITER; ++it) {
        k_demix<<<gD, 256>>>(Xr4, Xi4);
        k_phi<<<16, 256>>>();
        k_V<<<gV, 128>>>(Xr4, Xi4);
        k_Vsum<<<129, 256>>>();
        k_ip<<<17, 32>>>(it == N_ITER - 1 ? 1 : 0);
    }
    k_out<<<gO, 256>>>(Xr4, Xi4, out4);
}

// round 13
// speedup vs baseline: 1.0055x; 1.0055x over previous
#include <cuda_runtime.h>

// AuxIVA: K=4 sources, F=513 freqs, B=4000 frames, 5 iterations.
// d_in[0]=Xr (K,F,B) f32, d_in[1]=Xi (K,F,B) f32.
// Output: float32 (K,F,B) = real part of projected-back demixed signal.

#define K_DIM 4
#define F_DIM 513
#define B_DIM 4000
#define B4    (B_DIM / 4)          // 1000 float4 per (k,f) row
#define FB    (F_DIM * B_DIM)
#define FB4   (FB / 4)
#define KFB   (K_DIM * F_DIM * B_DIM)
#define N_ITER 5
#define FCH   57                   // f-chunks in k_demix
#define CHF   9                    // f per chunk (57*9 = 513)
#define NSPL  8                    // b-splits in k_V
#define NSLOT 32                   // warp slots per f in k_V (NSPL*4)

// ---------------- scratch ----------------
static __device__ float g_Whr[F_DIM * 16];             // [f][s][c]
static __device__ float g_Whi[F_DIM * 16];
static __device__ float g_part[FCH * K_DIM * B_DIM];   // [ch][k][b]
static __device__ float g_phi[K_DIM * B_DIM];          // 0.5/r, [k][b]
static __device__ float g_Vp[NSLOT * 64 * F_DIM];      // [slot][k*16+e][f]
static __device__ float g_V[64 * F_DIM];               // packed [k*16+e][f]
static __device__ float g_sclr[F_DIM * 4];             // [f][s]
static __device__ float g_scli[F_DIM * 4];

// Gauss-Jordan solve of 4x4 complex system, conditional-swap partial pivot.
static __device__ __forceinline__ void solve4(float Ar[4][4], float Ai[4][4],
                                              float ur[4], float ui[4]) {
#pragma unroll
    for (int j = 0; j < 4; j++) {
#pragma unroll
        for (int i = 0; i < 4; i++) {
            if (i > j) {
                float mj = Ar[j][j] * Ar[j][j] + Ai[j][j] * Ai[j][j];
                float mi = Ar[i][j] * Ar[i][j] + Ai[i][j] * Ai[i][j];
                if (mi > mj) {
#pragma unroll
                    for (int c = 0; c < 4; c++) {
                        float tr = Ar[j][c]; Ar[j][c] = Ar[i][c]; Ar[i][c] = tr;
                        float ti = Ai[j][c]; Ai[j][c] = Ai[i][c]; Ai[i][c] = ti;
                    }
                    float tr = ur[j]; ur[j] = ur[i]; ur[i] = tr;
                    float ti = ui[j]; ui[j] = ui[i]; ui[i] = ti;
                }
            }
        }
        float dr = Ar[j][j], di = Ai[j][j];
        float inv = 1.0f / (dr * dr + di * di);
        float pr = dr * inv, pi = -di * inv;
#pragma unroll
        for (int c = 0; c < 4; c++) {
            float ar = Ar[j][c], ai = Ai[j][c];
            Ar[j][c] = ar * pr - ai * pi;
            Ai[j][c] = ar * pi + ai * pr;
        }
        {
            float ar = ur[j], ai = ui[j];
            ur[j] = ar * pr - ai * pi;
            ui[j] = ar * pi + ai * pr;
        }
#pragma unroll
        for (int i = 0; i < 4; i++) {
            if (i != j) {
                float fr = Ar[i][j], fi = Ai[i][j];
#pragma unroll
                for (int c = 0; c < 4; c++) {
                    float ar = Ar[j][c], ai = Ai[j][c];
                    Ar[i][c] -= fr * ar - fi * ai;
                    Ai[i][c] -= fr * ai + fi * ar;
                }
                float ar = ur[j], ai = ui[j];
                ur[i] -= fr * ar - fi * ai;
                ui[i] -= fr * ai + fi * ar;
            }
        }
    }
}

// ---------------- kernels ----------------

static __global__ void k_init() {
    int i = blockIdx.x * blockDim.x + threadIdx.x;
    if (i < F_DIM * 16) {
        int rem = i & 15;
        g_Whr[i] = (rem == 0 || rem == 5 || rem == 10 || rem == 15) ? 1.f : 0.f;
        g_Whi[i] = 0.f;
    }
}

// part[ch][k][b] = sum over chunk's 9 f of |sum_c Wh[f,k,c] X[c,f,b]|^2
static __global__ void k_demix(const float4* __restrict__ Xr4,
                               const float4* __restrict__ Xi4) {
    const int ch  = blockIdx.x;                    // 0..56
    const int idx = blockIdx.y * 256 + threadIdx.x; // float4 index in b
    if (idx >= B4) return;

    float acc[4][4];                               // [s][sub-b]
#pragma unroll
    for (int s = 0; s < 4; s++)
#pragma unroll
        for (int u = 0; u < 4; u++) acc[s][u] = 0.f;

    const int f0 = ch * CHF;
    for (int fi = 0; fi < CHF; fi++) {
        const int f = f0 + fi;
        const int base4 = f * B4 + idx;
        float xr[4][4], xi[4][4];                  // [c][sub]
#pragma unroll
        for (int c = 0; c < 4; c++) {
            float4 tr = Xr4[c * FB4 + base4];
            float4 ti = Xi4[c * FB4 + base4];
            xr[c][0] = tr.x; xr[c][1] = tr.y; xr[c][2] = tr.z; xr[c][3] = tr.w;
            xi[c][0] = ti.x; xi[c][1] = ti.y; xi[c][2] = ti.z; xi[c][3] = ti.w;
        }
#pragma unroll
        for (int s = 0; s < 4; s++) {
            float wr[4], wi[4];
#pragma unroll
            for (int c = 0; c < 4; c++) {
                wr[c] = g_Whr[f * 16 + s * 4 + c];
                wi[c] = g_Whi[f * 16 + s * 4 + c];
            }
#pragma unroll
            for (int u = 0; u < 4; u++) {
                float yr = 0.f, yi = 0.f;
#pragma unroll
                for (int c = 0; c < 4; c++) {
                    yr += wr[c] * xr[c][u] - wi[c] * xi[c][u];
                    yi += wr[c] * xi[c][u] + wi[c] * xr[c][u];
                }
                acc[s][u] += yr * yr + yi * yi;
            }
        }
    }
    float4* P4 = (float4*)g_part;
#pragma unroll
    for (int s = 0; s < 4; s++) {
        float4 v;
        v.x = acc[s][0]; v.y = acc[s][1]; v.z = acc[s][2]; v.w = acc[s][3];
        P4[(ch * 4 + s) * B4 + idx] = v;
    }
}

// phi[k][b] = 0.5 / sqrt( sum_ch part[ch][k][b] )
static __global__ void k_phi() {
    int t = blockIdx.x * blockDim.x + threadIdx.x;     // (k*B4 + idx)
    if (t >= 4 * B4) return;
    const float4* P4 = (const float4*)g_part;
    const int k = t / B4, idx = t % B4;
    float4 s = make_float4(0.f, 0.f, 0.f, 0.f);
    for (int ch = 0; ch < FCH; ch++) {
        float4 v = P4[(ch * 4 + k) * B4 + idx];
        s.x += v.x; s.y += v.y; s.z += v.z; s.w += v.w;
    }
    float4 p;
    p.x = 0.5f * rsqrtf(s.x);
    p.y = 0.5f * rsqrtf(s.y);
    p.z = 0.5f * rsqrtf(s.z);
    p.w = 0.5f * rsqrtf(s.w);
    ((float4*)g_phi)[k * B4 + idx] = p;
}

// V partials: grid (F_DIM, NSPL), block 128. Each thread handles one float4
// of b (4 frames), computes the 16 Hermitian products ONCE, weights by all
// 4 phi's, warp-reduces, writes per-warp partials.
static __global__ void k_V(const float4* __restrict__ Xr4,
                           const float4* __restrict__ Xi4) {
    const int f = blockIdx.x;
    const int g = blockIdx.y * 128 + threadIdx.x;   // 0..1023 per f
    const int lane = threadIdx.x & 31;

    float acc[4][16];
#pragma unroll
    for (int k = 0; k < 4; k++)
#pragma unroll
        for (int e = 0; e < 16; e++) acc[k][e] = 0.f;

    if (g < B4) {
        const int base4 = f * B4 + g;
        float xr[4][4], xi[4][4];
#pragma unroll
        for (int c = 0; c < 4; c++) {
            float4 tr = Xr4[c * FB4 + base4];
            float4 ti = Xi4[c * FB4 + base4];
            xr[c][0] = tr.x; xr[c][1] = tr.y; xr[c][2] = tr.z; xr[c][3] = tr.w;
            xi[c][0] = ti.x; xi[c][1] = ti.y; xi[c][2] = ti.z; xi[c][3] = ti.w;
        }
        float ph[4][4];
#pragma unroll
        for (int k = 0; k < 4; k++) {
            float4 p = ((const float4*)g_phi)[k * B4 + g];
            ph[k][0] = p.x; ph[k][1] = p.y; ph[k][2] = p.z; ph[k][3] = p.w;
        }
#pragma unroll
        for (int u = 0; u < 4; u++) {
            float pr[16];
            pr[0]  = xr[0][u] * xr[0][u] + xi[0][u] * xi[0][u];
            pr[1]  = xr[1][u] * xr[1][u] + xi[1][u] * xi[1][u];
            pr[2]  = xr[2][u] * xr[2][u] + xi[2][u] * xi[2][u];
            pr[3]  = xr[3][u] * xr[3][u] + xi[3][u] * xi[3][u];
            pr[4]  = xr[0][u] * xr[1][u] + xi[0][u] * xi[1][u];
            pr[5]  = xi[0][u] * xr[1][u] - xr[0][u] * xi[1][u];
            pr[6]  = xr[0][u] * xr[2][u] + xi[0][u] * xi[2][u];
            pr[7]  = xi[0][u] * xr[2][u] - xr[0][u] * xi[2][u];
            pr[8]  = xr[0][u] * xr[3][u] + xi[0][u] * xi[3][u];
            pr[9]  = xi[0][u] * xr[3][u] - xr[0][u] * xi[3][u];
            pr[10] = xr[1][u] * xr[2][u] + xi[1][u] * xi[2][u];
            pr[11] = xi[1][u] * xr[2][u] - xr[1][u] * xi[2][u];
            pr[12] = xr[1][u] * xr[3][u] + xi[1][u] * xi[3][u];
            pr[13] = xi[1][u] * xr[3][u] - xr[1][u] * xi[3][u];
            pr[14] = xr[2][u] * xr[3][u] + xi[2][u] * xi[3][u];
            pr[15] = xi[2][u] * xr[3][u] - xr[2][u] * xi[3][u];
#pragma unroll
            for (int k = 0; k < 4; k++) {
                float p = ph[k][u];
#pragma unroll
                for (int e = 0; e < 16; e++)
                    acc[k][e] += p * pr[e];
            }
        }
    }

#pragma unroll
    for (int k = 0; k < 4; k++)
#pragma unroll
        for (int e = 0; e < 16; e++) {
#pragma unroll
            for (int off = 16; off > 0; off >>= 1)
                acc[k][e] += __shfl_down_sync(0xffffffffu, acc[k][e], off);
        }

    if (lane == 0) {
        const int slot = blockIdx.y * 4 + (threadIdx.x >> 5);   // 0..31
#pragma unroll
        for (int k = 0; k < 4; k++)
#pragma unroll
            for (int e = 0; e < 16; e++)
                g_Vp[(slot * 64 + k * 16 + e) * F_DIM + f] = acc[k][e];
    }
}

// Sum the 32 per-warp partials -> packed V (with 1/B scaling).
static __global__ void k_Vsum() {
    int t = blockIdx.x * blockDim.x + threadIdx.x;     // e64 * F_DIM + f
    if (t >= 64 * F_DIM) return;
    const int e = t / F_DIM, f = t % F_DIM;
    float s = 0.f;
#pragma unroll
    for (int slot = 0; slot < NSLOT; slot++)
        s += g_Vp[(slot * 64 + e) * F_DIM + f];
    g_V[e * F_DIM + f] = s * (1.0f / (float)B_DIM);
}

// IP updates per frequency; reads packed V, expands Hermitian in registers.
static __global__ void k_ip(int compute_scale) {
    __shared__ float sWr[16][32], sWi[16][32];
    const int tid = threadIdx.x;          // 32
    const int f = blockIdx.x * 32 + tid;
    if (f >= F_DIM) return;

#pragma unroll
    for (int e = 0; e < 16; e++) {
        sWr[e][tid] = g_Whr[f * 16 + e];
        sWi[e][tid] = g_Whi[f * 16 + e];
    }

    for (int k = 0; k < 4; k++) {
        float pk[16];
#pragma unroll
        for (int e = 0; e < 16; e++)
            pk[e] = g_V[(k * 16 + e) * F_DIM + f];
        // expand packed -> Hermitian Vk
        float Vr[4][4], Vi[4][4];
        Vr[0][0] = pk[0]; Vi[0][0] = 0.f;
        Vr[1][1] = pk[1]; Vi[1][1] = 0.f;
        Vr[2][2] = pk[2]; Vi[2][2] = 0.f;
        Vr[3][3] = pk[3]; Vi[3][3] = 0.f;
        Vr[0][1] = pk[4];  Vi[0][1] =  pk[5];  Vr[1][0] = pk[4];  Vi[1][0] = -pk[5];
        Vr[0][2] = pk[6];  Vi[0][2] =  pk[7];  Vr[2][0] = pk[6];  Vi[2][0] = -pk[7];
        Vr[0][3] = pk[8];  Vi[0][3] =  pk[9];  Vr[3][0] = pk[8];  Vi[3][0] = -pk[9];
        Vr[1][2] = pk[10]; Vi[1][2] =  pk[11]; Vr[2][1] = pk[10]; Vi[2][1] = -pk[11];
        Vr[1][3] = pk[12]; Vi[1][3] =  pk[13]; Vr[3][1] = pk[12]; Vi[3][1] = -pk[13];
        Vr[2][3] = pk[14]; Vi[2][3] =  pk[15]; Vr[3][2] = pk[14]; Vi[3][2] = -pk[15];

        float Mr[4][4], Mi[4][4];
#pragma unroll
        for (int i = 0; i < 4; i++)
#pragma unroll
            for (int j = 0; j < 4; j++) {
                float ar = 0.f, ai = 0.f;
#pragma unroll
                for (int c = 0; c < 4; c++) {
                    float wr = sWr[i * 4 + c][tid], wi = sWi[i * 4 + c][tid];
                    ar += wr * Vr[c][j] - wi * Vi[c][j];
                    ai += wr * Vi[c][j] + wi * Vr[c][j];
                }
                Mr[i][j] = ar;
                Mi[i][j] = ai;
            }
        float ur[4], ui[4];
#pragma unroll
        for (int e = 0; e < 4; e++) { ur[e] = (e == k) ? 1.f : 0.f; ui[e] = 0.f; }
        solve4(Mr, Mi, ur, ui);
        float q = 0.f;
#pragma unroll
        for (int c = 0; c < 4; c++) {
            float tr = 0.f, ti = 0.f;
#pragma unroll
            for (int j = 0; j < 4; j++) {
                tr += Vr[c][j] * ur[j] - Vi[c][j] * ui[j];
                ti += Vr[c][j] * ui[j] + Vi[c][j] * ur[j];
            }
            q += ur[c] * tr + ui[c] * ti;
        }
        float invd = rsqrtf(q);
#pragma unroll
        for (int c = 0; c < 4; c++) {
            sWr[k * 4 + c][tid] =  ur[c] * invd;
            sWi[k * 4 + c][tid] = -ui[c] * invd;
        }
    }

#pragma unroll
    for (int e = 0; e < 16; e++) {
        g_Whr[f * 16 + e] = sWr[e][tid];
        g_Whi[f * 16 + e] = sWi[e][tid];
    }

    if (compute_scale) {
        float Ar[4][4], Ai[4][4], vr[4], vi[4];
#pragma unroll
        for (int i = 0; i < 4; i++)
#pragma unroll
            for (int j = 0; j < 4; j++) {
                Ar[i][j] = sWr[i * 4 + j][tid];
                Ai[i][j] = sWi[i * 4 + j][tid];
            }
#pragma unroll
        for (int e = 0; e < 4; e++) { vr[e] = (e == 0) ? 1.f : 0.f; vi[e] = 0.f; }
        solve4(Ar, Ai, vr, vi);
#pragma unroll
        for (int c = 0; c < 4; c++) {
            g_sclr[f * 4 + c] = vr[c];
            g_scli[f * 4 + c] = vi[c];
        }
    }
}

// out[s,f,b] = Re( (sum_c Wh[f,s,c] X[c,f,b]) * scale[f,s] )
static __global__ void k_out(const float4* __restrict__ Xr4,
                             const float4* __restrict__ Xi4,
                             float4* __restrict__ out4) {
    const int f   = blockIdx.x;
    const int idx = blockIdx.y * 256 + threadIdx.x;
    if (idx >= B4) return;

    const int base4 = f * B4 + idx;
    float xr[4][4], xi[4][4];
#pragma unroll
    for (int c = 0; c < 4; c++) {
        float4 tr = Xr4[c * FB4 + base4];
        float4 ti = Xi4[c * FB4 + base4];
        xr[c][0] = tr.x; xr[c][1] = tr.y; xr[c][2] = tr.z; xr[c][3] = tr.w;
        xi[c][0] = ti.x; xi[c][1] = ti.y; xi[c][2] = ti.z; xi[c][3] = ti.w;
    }
#pragma unroll
    for (int s = 0; s < 4; s++) {
        float wr[4], wi[4];
#pragma unroll
        for (int c = 0; c < 4; c++) {
            wr[c] = g_Whr[f * 16 + s * 4 + c];
            wi[c] = g_Whi[f * 16 + s * 4 + c];
        }
        float scr = g_sclr[f * 4 + s];
        float sci = g_scli[f * 4 + s];
        float o[4];
#pragma unroll
        for (int u = 0; u < 4; u++) {
            float yr = 0.f, yi = 0.f;
#pragma unroll
            for (int c = 0; c < 4; c++) {
                yr += wr[c] * xr[c][u] - wi[c] * xi[c][u];
                yi += wr[c] * xi[c][u] + wi[c] * xr[c][u];
            }
            o[u] = yr * scr - yi * sci;
        }
        float4 v;
        v.x = o[0]; v.y = o[1]; v.z = o[2]; v.w = o[3];
        out4[s * FB4 + base4] = v;
    }
}

// ---------------- launch ----------------
extern "C" void kernel_launch(void* const* d_in, const int* in_sizes, int n_in,
                              void* d_out, int out_size) {
    if (n_in < 2) return;
    const float4* Xr4 = (const float4*)d_in[0];
    const float4* Xi4 = (const float4*)d_in[1];
    float4* out4 = (float4*)d_out;

    dim3 gD(FCH, 4);          // k_demix: 57 x 4 blocks, 256 thr
    dim3 gV(F_DIM, NSPL);     // k_V:     513 x 8 blocks, 128 thr
    dim3 gO(F_DIM, 4);        // k_out:   513 x 4 blocks, 256 thr

    k_init<<<33, 256>>>();
    for (int it = 0; it < N_ITER; ++it) {
        k_demix<<<gD, 256>>>(Xr4, Xi4);
        k_phi<<<16, 256>>>();
        k_V<<<gV, 128>>>(Xr4, Xi4);
        k_Vsum<<<129, 256>>>();
        k_ip<<<17, 32>>>(it == N_ITER - 1 ? 1 : 0);
    }
    k_out<<<gO, 256>>>(Xr4, Xi4, out4);
}